// round 5
// baseline (speedup 1.0000x reference)
#include <cuda_runtime.h>
#include <cstdint>

#define NN 100000
#define EE 800000
#define HH 4
#define FF 64
#define KTOT 320          // 4*64 (attention heads) + 64 (global branch)
#define SCAN_B 98         // ceil(100000/1024)

// ---------------- device scratch (static: no runtime allocation) -------------
__device__ __align__(16) float g_wsrc[HH*FF];
__device__ __align__(16) float g_wdst[HH*FF];
__device__ __align__(16) float g_Mall[KTOT*FF];   // combined projection [k][o]
__device__ __align__(16) unsigned g_Bfrag[40*8*32*2];  // tf32 B fragments, mma-order
__device__ __align__(16) float g_bias[FF];
__device__ __align__(16) float4 g_ssrc4[NN];
__device__ __align__(16) float4 g_sdst4[NN];
__device__ int   g_is64;
__device__ int   g_eidx[2*EE];    // decoded edge indices: [src row | dst row]
__device__ int   g_cnt[NN];
__device__ int   g_rowptr[NN+1];
__device__ int   g_cursor[NN];
__device__ int   g_bsum[SCAN_B];
__device__ float g_deg[NN];
__device__ int   g_esrc[EE];
__device__ __align__(16) float4 g_escore[EE];
__device__ __align__(16) float g_A[(size_t)NN*KTOT];  // [N][320]: agg heads | g2
__device__ __align__(16) float g_g1[(size_t)NN*FF];

// ---------------- helpers ----------------------------------------------------
__device__ __forceinline__ float wredmax(float v){
#pragma unroll
    for (int o = 16; o > 0; o >>= 1) v = fmaxf(v, __shfl_xor_sync(0xffffffffu, v, o));
    return v;
}
__device__ __forceinline__ float wredsum(float v){
#pragma unroll
    for (int o = 16; o > 0; o >>= 1) v += __shfl_xor_sync(0xffffffffu, v, o);
    return v;
}
__device__ __forceinline__ unsigned f2tf32(float f){
    unsigned r; asm("cvt.rna.tf32.f32 %0, %1;" : "=r"(r) : "f"(f)); return r;
}
__device__ __forceinline__ float lrelu(float v){ return v > 0.f ? v : 0.2f * v; }

// ---------------- K-1a: detect int32 vs int64 edge_index ---------------------
__global__ void k_detect(const int* __restrict__ ei32){
    int t = threadIdx.x;                  // 0..31
    int v = ei32[2*t + 1];
    unsigned any = __ballot_sync(0xffffffffu, v != 0);
    if (t == 0) g_is64 = (any == 0u) ? 1 : 0;
}

// ---------------- K-1b: decode + clamp indices into g_eidx -------------------
__global__ void k_decode(const void* __restrict__ ei){
    int e = blockIdx.x*blockDim.x + threadIdx.x;
    if (e >= 2*EE) return;
    int v;
    if (g_is64) v = (int)((const long long*)ei)[e];
    else        v = ((const int*)ei)[e];
    v = (v < 0) ? 0 : (v >= NN ? NN-1 : v);   // defensive clamp
    g_eidx[e] = v;
}

// ---------------- K0a: w_src/w_dst = W_att[h] @ a_{src,dst}[h] ---------------
__global__ void k_wvec(const float* __restrict__ W_att,
                       const float* __restrict__ a_src,
                       const float* __restrict__ a_dst){
    int b = blockIdx.x;           // 0..7
    int h = b >> 1, sel = b & 1;
    int i = threadIdx.x;          // 0..63
    const float* W = W_att + (size_t)h*FF*FF + (size_t)i*FF;
    const float* a = (sel ? a_dst : a_src) + h*FF;
    float s = 0.f;
#pragma unroll 8
    for (int o = 0; o < FF; o++) s += W[o]*a[o];
    (sel ? g_wdst : g_wsrc)[h*FF + i] = s;
}

// ---------------- K0b: Mall rows + bias --------------------------------------
__global__ void k_mall(const float* __restrict__ W_att,
                       const float* __restrict__ W_g,
                       const float* __restrict__ W_w,
                       const float* __restrict__ b_g,
                       const float* __restrict__ b_w){
    int r = blockIdx.x;   // 0..320 (320 == bias row)
    int o = threadIdx.x;  // 0..63
    if (r < 256) {
        int h = r >> 6, i = r & 63;
        const float* wa = W_att + (size_t)h*FF*FF + (size_t)i*FF;
        float s = 0.f;
#pragma unroll 8
        for (int j = 0; j < FF; j++) s += wa[j] * W_w[(size_t)j*FF + o];
        g_Mall[(size_t)r*FF + o] = 0.25f * s;
    } else if (r < 320) {
        int i = r - 256;
        float s = 0.f;
#pragma unroll 8
        for (int j = 0; j < FF; j++) s += W_g[(size_t)i*FF + j] * W_w[(size_t)(FF+j)*FF + o];
        g_Mall[(size_t)r*FF + o] = s;
    } else {
        float s = b_w[o];
#pragma unroll 8
        for (int j = 0; j < FF; j++) s += b_g[j] * W_w[(size_t)(FF+j)*FF + o];
        g_bias[o] = s;
    }
}

// ---------------- K0c: permute Mall into tf32 mma B-fragments ----------------
// m16n8k8.row.col B fragment: lane = gid*4+tig holds {B[k=tig][n=gid], B[k=tig+4][n=gid]}
__global__ void k_bfrag(){
    int c = blockIdx.x;           // k8 chunk 0..39
    int t = threadIdx.x;          // 0..255
    int n8 = t >> 5, lane = t & 31;
    int tig = lane & 3, gid = lane >> 2;
    int n = n8*8 + gid;
    float b0 = g_Mall[(size_t)(c*8 + tig    )*FF + n];
    float b1 = g_Mall[(size_t)(c*8 + tig + 4)*FF + n];
    size_t idx = ((size_t)(c*8 + n8)*32 + lane)*2;
    g_Bfrag[idx]   = f2tf32(b0);
    g_Bfrag[idx+1] = f2tf32(b1);
}

// ---------------- K1: per-node attention logits s_src/s_dst ------------------
__global__ void k_score(const float* __restrict__ x){
    int warp = threadIdx.x >> 5, lane = threadIdx.x & 31;
    int n = blockIdx.x*8 + warp;
    if (n >= NN) return;
    float2 xv = *(const float2*)(x + (size_t)n*FF + lane*2);
    float p[8];
#pragma unroll
    for (int h = 0; h < 4; h++) {
        float2 w = *(const float2*)(g_wsrc + h*FF + lane*2);
        p[h] = xv.x*w.x + xv.y*w.y;
    }
#pragma unroll
    for (int h = 0; h < 4; h++) {
        float2 w = *(const float2*)(g_wdst + h*FF + lane*2);
        p[4+h] = xv.x*w.x + xv.y*w.y;
    }
#pragma unroll
    for (int k = 0; k < 8; k++) p[k] = wredsum(p[k]);
    if (lane == 0) {
        g_ssrc4[n] = make_float4(p[0], p[1], p[2], p[3]);
        g_sdst4[n] = make_float4(p[4], p[5], p[6], p[7]);
    }
}

// ---------------- K2: zero histogram -----------------------------------------
__global__ void k_zero(){
    int i = blockIdx.x*blockDim.x + threadIdx.x;
    if (i < NN) g_cnt[i] = 0;
}

// ---------------- K3: dst histogram ------------------------------------------
__global__ void k_hist(){
    int e = blockIdx.x*blockDim.x + threadIdx.x;
    if (e < EE) atomicAdd(&g_cnt[g_eidx[EE + e]], 1);
}

// ---------------- K4: scan (3 stages) ----------------------------------------
__global__ void k_scan1(){
    __shared__ int sh[1024];
    int t = threadIdx.x;
    int i = blockIdx.x*1024 + t;
    int v = (i < NN) ? g_cnt[i] : 0;
    sh[t] = v; __syncthreads();
#pragma unroll
    for (int off = 1; off < 1024; off <<= 1) {
        int u = (t >= off) ? sh[t - off] : 0;
        __syncthreads();
        sh[t] += u;
        __syncthreads();
    }
    if (i < NN) g_rowptr[i+1] = sh[t];
    if (t == 1023) g_bsum[blockIdx.x] = sh[1023];
}
__global__ void k_scan2(){
    int run = 0;
    for (int b = 0; b < SCAN_B; b++) { int t = g_bsum[b]; g_bsum[b] = run; run += t; }
}
__global__ void k_scan3(){
    int t = threadIdx.x;
    int i = blockIdx.x*1024 + t;
    if (i < NN) {
        int incl = g_rowptr[i+1] + g_bsum[blockIdx.x];
        g_rowptr[i+1] = incl;
        int c = g_cnt[i];
        g_cursor[i] = incl - c;
        g_deg[i] = (float)(c > 0 ? c : 1);
        if (i == 0) g_rowptr[0] = 0;
    }
}

// ---------------- K5: scatter edges into CSR, with precomputed scores --------
__global__ void k_scatter(){
    int e = blockIdx.x*blockDim.x + threadIdx.x;
    if (e >= EE) return;
    int s = g_eidx[e];
    int d = g_eidx[EE + e];
    int p = atomicAdd(&g_cursor[d], 1);
    g_esrc[p] = s;
    float4 a = g_ssrc4[s];
    float4 b = g_sdst4[d];
    float4 sc;
    sc.x = lrelu(a.x + b.x); sc.y = lrelu(a.y + b.y);
    sc.z = lrelu(a.z + b.z); sc.w = lrelu(a.w + b.w);
    g_escore[p] = sc;
}

// ---------------- K6: segment softmax + weighted aggregate + hop-1 -----------
__global__ void k_att(const float* __restrict__ x){
    int warp = threadIdx.x >> 5, lane = threadIdx.x & 31;
    int n = blockIdx.x*8 + warp;
    if (n >= NN) return;
    int beg = g_rowptr[n], end = g_rowptr[n+1];
    size_t arow = (size_t)n*KTOT;
    if (beg == end) {
        float2 z = make_float2(0.f, 0.f);
#pragma unroll
        for (int h = 0; h < 4; h++) *(float2*)(g_A + arow + h*FF + lane*2) = z;
        *(float2*)(g_g1 + (size_t)n*FF + lane*2) = z;
        return;
    }
    const float NEG = -1e30f;
    float4 mx = make_float4(NEG, NEG, NEG, NEG);
    for (int j = beg + lane; j < end; j += 32) {
        float4 s = g_escore[j];
        mx.x = fmaxf(mx.x, s.x); mx.y = fmaxf(mx.y, s.y);
        mx.z = fmaxf(mx.z, s.z); mx.w = fmaxf(mx.w, s.w);
    }
    mx.x = wredmax(mx.x); mx.y = wredmax(mx.y);
    mx.z = wredmax(mx.z); mx.w = wredmax(mx.w);
    float4 den = make_float4(0.f, 0.f, 0.f, 0.f);
    for (int j = beg + lane; j < end; j += 32) {
        float4 s = g_escore[j];
        float4 e;
        e.x = __expf(s.x - mx.x); e.y = __expf(s.y - mx.y);
        e.z = __expf(s.z - mx.z); e.w = __expf(s.w - mx.w);
        den.x += e.x; den.y += e.y; den.z += e.z; den.w += e.w;
        g_escore[j] = e;
    }
    den.x = wredsum(den.x); den.y = wredsum(den.y);
    den.z = wredsum(den.z); den.w = wredsum(den.w);
    __syncwarp();
    float4 inv;
    inv.x = 1.f/fmaxf(den.x, 1e-16f); inv.y = 1.f/fmaxf(den.y, 1e-16f);
    inv.z = 1.f/fmaxf(den.z, 1e-16f); inv.w = 1.f/fmaxf(den.w, 1e-16f);

    float2 a0 = make_float2(0,0), a1 = a0, a2 = a0, a3 = a0, ag = a0;
    for (int j = beg; j < end; j++) {
        int s = g_esrc[j];              // uniform across warp -> broadcast
        float4 al = g_escore[j];        // uniform across warp
        float2 v = *(const float2*)(x + (size_t)s*FF + lane*2);
        a0.x += al.x*v.x; a0.y += al.x*v.y;
        a1.x += al.y*v.x; a1.y += al.y*v.y;
        a2.x += al.z*v.x; a2.y += al.z*v.y;
        a3.x += al.w*v.x; a3.y += al.w*v.y;
        ag.x += v.x;      ag.y += v.y;
    }
    *(float2*)(g_A + arow + 0*FF + lane*2) = make_float2(a0.x*inv.x, a0.y*inv.x);
    *(float2*)(g_A + arow + 1*FF + lane*2) = make_float2(a1.x*inv.y, a1.y*inv.y);
    *(float2*)(g_A + arow + 2*FF + lane*2) = make_float2(a2.x*inv.z, a2.y*inv.z);
    *(float2*)(g_A + arow + 3*FF + lane*2) = make_float2(a3.x*inv.w, a3.y*inv.w);
    float dinv = 1.f / g_deg[n];
    *(float2*)(g_g1 + (size_t)n*FF + lane*2) = make_float2(ag.x*dinv, ag.y*dinv);
}

// ---------------- K7: hop-2 mean aggregation into A cols 256..319 ------------
__global__ void k_hop2(){
    int warp = threadIdx.x >> 5, lane = threadIdx.x & 31;
    int n = blockIdx.x*8 + warp;
    if (n >= NN) return;
    int beg = g_rowptr[n], end = g_rowptr[n+1];
    float2 ag = make_float2(0.f, 0.f);
    for (int j = beg; j < end; j++) {
        int s = g_esrc[j];
        float2 v = *(const float2*)(g_g1 + (size_t)s*FF + lane*2);
        ag.x += v.x; ag.y += v.y;
    }
    float dinv = 1.f / g_deg[n];
    *(float2*)(g_A + (size_t)n*KTOT + 256 + lane*2) = make_float2(ag.x*dinv, ag.y*dinv);
}

// ---------------- K8: out = A[N,320] @ Mall[320,64] + bias  (tf32 mma) -------
// 256 threads, block tile 128x64, 8 warps in 4x2; per-warp 2x4 tiles of m16n8.
__global__ __launch_bounds__(256) void k_gemm(float* __restrict__ out){
    __shared__ float As[128][33];
    int t = threadIdx.x, warp = t >> 5, lane = t & 31;
    int wm = warp >> 1, wn = warp & 1;
    int gid = lane >> 2, tig = lane & 3;
    int blockRow = blockIdx.x * 128;

    float c[2][4][4];
#pragma unroll
    for (int mt = 0; mt < 2; mt++)
#pragma unroll
        for (int nt = 0; nt < 4; nt++)
#pragma unroll
            for (int i = 0; i < 4; i++) c[mt][nt][i] = 0.f;

    for (int kb = 0; kb < 10; kb++) {
        // stage 128x32 A tile (256 threads x 4 rows, float4 per thread)
#pragma unroll
        for (int ii = 0; ii < 4; ii++) {
            int r  = (t >> 3) + ii*32;
            int c4 = (t & 7) * 4;
            int gr = blockRow + r;
            float4 v = make_float4(0.f, 0.f, 0.f, 0.f);
            if (gr < NN) v = *(const float4*)(g_A + (size_t)gr*KTOT + kb*32 + c4);
            As[r][c4] = v.x; As[r][c4+1] = v.y; As[r][c4+2] = v.z; As[r][c4+3] = v.w;
        }
        __syncthreads();
#pragma unroll
        for (int ks = 0; ks < 4; ks++) {
            int kk = ks*8;
            int cch = kb*4 + ks;
            unsigned ua[2][4];
#pragma unroll
            for (int mt = 0; mt < 2; mt++) {
                int r0 = wm*32 + mt*16 + gid;
                ua[mt][0] = f2tf32(As[r0    ][kk+tig]);
                ua[mt][1] = f2tf32(As[r0 + 8][kk+tig]);
                ua[mt][2] = f2tf32(As[r0    ][kk+tig+4]);
                ua[mt][3] = f2tf32(As[r0 + 8][kk+tig+4]);
            }
#pragma unroll
            for (int nt = 0; nt < 4; nt++) {
                int n8 = wn*4 + nt;
                const unsigned* bp = g_Bfrag + ((size_t)(cch*8 + n8)*32 + lane)*2;
                unsigned b0 = bp[0], b1 = bp[1];
#pragma unroll
                for (int mt = 0; mt < 2; mt++) {
                    asm volatile(
                        "mma.sync.aligned.m16n8k8.row.col.f32.tf32.tf32.f32 "
                        "{%0,%1,%2,%3},{%4,%5,%6,%7},{%8,%9},{%0,%1,%2,%3};"
                        : "+f"(c[mt][nt][0]), "+f"(c[mt][nt][1]),
                          "+f"(c[mt][nt][2]), "+f"(c[mt][nt][3])
                        : "r"(ua[mt][0]), "r"(ua[mt][1]), "r"(ua[mt][2]), "r"(ua[mt][3]),
                          "r"(b0), "r"(b1));
                }
            }
        }
        __syncthreads();
    }
    // epilogue: bias + float2 stores
#pragma unroll
    for (int mt = 0; mt < 2; mt++) {
#pragma unroll
        for (int nt = 0; nt < 4; nt++) {
            int col = wn*32 + nt*8 + tig*2;
            float b0 = g_bias[col], b1 = g_bias[col+1];
            int r0 = blockRow + wm*32 + mt*16 + gid;
            if (r0 < NN)
                *(float2*)(out + (size_t)r0*FF + col) =
                    make_float2(c[mt][nt][0] + b0, c[mt][nt][1] + b1);
            int r1 = r0 + 8;
            if (r1 < NN)
                *(float2*)(out + (size_t)r1*FF + col) =
                    make_float2(c[mt][nt][2] + b0, c[mt][nt][3] + b1);
        }
    }
}

// ---------------- launch ------------------------------------------------------
extern "C" void kernel_launch(void* const* d_in, const int* in_sizes, int n_in,
                              void* d_out, int out_size){
    const float* x     = (const float*)d_in[0];
    const void*  ei    = d_in[1];
    const float* W_att = (const float*)d_in[2];
    const float* a_src = (const float*)d_in[3];
    const float* a_dst = (const float*)d_in[4];
    const float* W_g   = (const float*)d_in[5];
    const float* b_g   = (const float*)d_in[6];
    const float* W_w   = (const float*)d_in[7];
    const float* b_w   = (const float*)d_in[8];
    float* out = (float*)d_out;

    k_detect <<<1, 32>>>((const int*)ei);
    k_decode <<<(2*EE + 255)/256, 256>>>(ei);
    k_wvec   <<<8, 64>>>(W_att, a_src, a_dst);
    k_mall   <<<321, 64>>>(W_att, W_g, W_w, b_g, b_w);
    k_bfrag  <<<40, 256>>>();
    k_score  <<<(NN + 7)/8, 256>>>(x);
    k_zero   <<<(NN + 255)/256, 256>>>();
    k_hist   <<<(EE + 255)/256, 256>>>();
    k_scan1  <<<SCAN_B, 1024>>>();
    k_scan2  <<<1, 1>>>();
    k_scan3  <<<SCAN_B, 1024>>>();
    k_scatter<<<(EE + 255)/256, 256>>>();
    k_att    <<<(NN + 7)/8, 256>>>(x);
    k_hop2   <<<(NN + 7)/8, 256>>>();
    k_gemm   <<<(NN + 127)/128, 256>>>(out);
}

// round 6
// speedup vs baseline: 1.0620x; 1.0620x over previous
#include <cuda_runtime.h>
#include <cstdint>

#define NN 100000
#define EE 800000
#define HH 4
#define FF 64
#define KTOT 320          // 4*64 (attention heads) + 64 (global branch)
#define SCAN_B 98         // ceil(100000/1024)

// ---------------- device scratch (static: no runtime allocation) -------------
__device__ __align__(16) float g_wsrc[HH*FF];
__device__ __align__(16) float g_wdst[HH*FF];
__device__ __align__(16) float g_Mall[KTOT*FF];   // combined projection [k][o]
__device__ __align__(16) float g_bias[FF];
__device__ __align__(16) float4 g_ssrc4[NN];
__device__ __align__(16) float4 g_sdst4[NN];
__device__ int   g_eidx[2*EE];    // decoded edge indices: [src row | dst row]
__device__ int   g_cnt[NN];
__device__ int   g_rowptr[NN+1];
__device__ int   g_cursor[NN];
__device__ int   g_bsum[SCAN_B];
__device__ float g_deg[NN];
__device__ int   g_esrc[EE];
__device__ __align__(16) float4 g_escore[EE];
__device__ __align__(16) float g_A[(size_t)NN*KTOT];  // [N][320]: agg heads | g2
__device__ __align__(16) float g_g1[(size_t)NN*FF];

// ---------------- helpers ----------------------------------------------------
__device__ __forceinline__ float wredmax(float v){
#pragma unroll
    for (int o = 16; o > 0; o >>= 1) v = fmaxf(v, __shfl_xor_sync(0xffffffffu, v, o));
    return v;
}
__device__ __forceinline__ float wredsum(float v){
#pragma unroll
    for (int o = 16; o > 0; o >>= 1) v += __shfl_xor_sync(0xffffffffu, v, o);
    return v;
}
__device__ __forceinline__ float lrelu(float v){ return v > 0.f ? v : 0.2f * v; }

// ---------------- K1: decode (+dtype detect) + dst histogram -----------------
// dtype probe: for int64 ids < 2^31 every odd 32-bit word is 0; for an int32
// buffer odd words are random node ids. Per-warp redundant check, L2-broadcast.
__global__ void k_decode(const void* __restrict__ ei){
    int lane = threadIdx.x & 31;
    int probe = ((const int*)ei)[2*lane + 1];
    bool is64 = (__ballot_sync(0xffffffffu, probe != 0) == 0u);
    int e = blockIdx.x*blockDim.x + threadIdx.x;
    if (e >= 2*EE) return;
    int v;
    if (is64) v = (int)((const long long*)ei)[e];
    else      v = ((const int*)ei)[e];
    v = (v < 0) ? 0 : (v >= NN ? NN-1 : v);   // defensive clamp
    g_eidx[e] = v;
    if (e >= EE) atomicAdd(&g_cnt[v], 1);     // dst histogram fused
}

// ---------------- K0: zero histogram (must precede k_decode) -----------------
__global__ void k_zero(){
    int i = blockIdx.x*blockDim.x + threadIdx.x;
    if (i < NN) g_cnt[i] = 0;
}

// ---------------- K2a: w_src/w_dst = W_att[h] @ a_{src,dst}[h] ---------------
__global__ void k_wvec(const float* __restrict__ W_att,
                       const float* __restrict__ a_src,
                       const float* __restrict__ a_dst){
    int b = blockIdx.x;           // 0..7
    int h = b >> 1, sel = b & 1;
    int i = threadIdx.x;          // 0..63
    const float* W = W_att + (size_t)h*FF*FF + (size_t)i*FF;
    const float* a = (sel ? a_dst : a_src) + h*FF;
    float s = 0.f;
#pragma unroll
    for (int o = 0; o < FF; o++) s += W[o]*a[o];
    (sel ? g_wdst : g_wsrc)[h*FF + i] = s;
}

// ---------------- K2b: Mall rows + bias (4 rows per 256-thread block) --------
__global__ __launch_bounds__(256) void k_mall(const float* __restrict__ W_att,
                       const float* __restrict__ W_g,
                       const float* __restrict__ W_w,
                       const float* __restrict__ b_g,
                       const float* __restrict__ b_w){
    int r = blockIdx.x*4 + (threadIdx.x >> 6);  // 0..335 (valid 0..320)
    int o = threadIdx.x & 63;
    if (r > 320) return;
    if (r < 256) {
        int h = r >> 6, i = r & 63;
        const float* wa = W_att + (size_t)h*FF*FF + (size_t)i*FF;
        float s = 0.f;
#pragma unroll
        for (int j = 0; j < FF; j++) s += wa[j] * W_w[(size_t)j*FF + o];
        g_Mall[(size_t)r*FF + o] = 0.25f * s;
    } else if (r < 320) {
        int i = r - 256;
        float s = 0.f;
#pragma unroll
        for (int j = 0; j < FF; j++) s += W_g[(size_t)i*FF + j] * W_w[(size_t)(FF+j)*FF + o];
        g_Mall[(size_t)r*FF + o] = s;
    } else {
        float s = b_w[o];
#pragma unroll
        for (int j = 0; j < FF; j++) s += b_g[j] * W_w[(size_t)(FF+j)*FF + o];
        g_bias[o] = s;
    }
}

// ---------------- K3: per-node attention logits s_src/s_dst ------------------
__global__ void k_score(const float* __restrict__ x){
    int warp = threadIdx.x >> 5, lane = threadIdx.x & 31;
    int n = blockIdx.x*8 + warp;
    if (n >= NN) return;
    float2 xv = *(const float2*)(x + (size_t)n*FF + lane*2);
    float p[8];
#pragma unroll
    for (int h = 0; h < 4; h++) {
        float2 w = *(const float2*)(g_wsrc + h*FF + lane*2);
        p[h] = xv.x*w.x + xv.y*w.y;
    }
#pragma unroll
    for (int h = 0; h < 4; h++) {
        float2 w = *(const float2*)(g_wdst + h*FF + lane*2);
        p[4+h] = xv.x*w.x + xv.y*w.y;
    }
#pragma unroll
    for (int k = 0; k < 8; k++) p[k] = wredsum(p[k]);
    if (lane == 0) {
        g_ssrc4[n] = make_float4(p[0], p[1], p[2], p[3]);
        g_sdst4[n] = make_float4(p[4], p[5], p[6], p[7]);
    }
}

// ---------------- K4: scan (3 stages, shfl-based) ----------------------------
__global__ void k_scan1(){
    __shared__ int wsum[32];
    int t = threadIdx.x, lane = t & 31, w = t >> 5;
    int i = blockIdx.x*1024 + t;
    int v = (i < NN) ? g_cnt[i] : 0;
    int xv = v;
#pragma unroll
    for (int o = 1; o < 32; o <<= 1) {
        int u = __shfl_up_sync(0xffffffffu, xv, o);
        if (lane >= o) xv += u;
    }
    if (lane == 31) wsum[w] = xv;
    __syncthreads();
    if (w == 0) {
        int y = wsum[lane];
#pragma unroll
        for (int o = 1; o < 32; o <<= 1) {
            int u = __shfl_up_sync(0xffffffffu, y, o);
            if (lane >= o) y += u;
        }
        wsum[lane] = y;
    }
    __syncthreads();
    int incl = xv + (w > 0 ? wsum[w-1] : 0);
    if (i < NN) g_rowptr[i+1] = incl;
    if (t == 1023) g_bsum[blockIdx.x] = incl;
}
__global__ void k_scan2(){          // 1 block, 128 threads, exclusive scan
    __shared__ int wsum[4];
    int t = threadIdx.x, lane = t & 31, w = t >> 5;
    int v = (t < SCAN_B) ? g_bsum[t] : 0;
    int xv = v;
#pragma unroll
    for (int o = 1; o < 32; o <<= 1) {
        int u = __shfl_up_sync(0xffffffffu, xv, o);
        if (lane >= o) xv += u;
    }
    if (lane == 31) wsum[w] = xv;
    __syncthreads();
    int pre = 0;
#pragma unroll
    for (int k = 0; k < 4; k++) if (k < w) pre += wsum[k];
    if (t < SCAN_B) g_bsum[t] = xv + pre - v;   // exclusive
}
__global__ void k_scan3(){
    int t = threadIdx.x;
    int i = blockIdx.x*1024 + t;
    if (i < NN) {
        int incl = g_rowptr[i+1] + g_bsum[blockIdx.x];
        g_rowptr[i+1] = incl;
        int c = g_cnt[i];
        g_cursor[i] = incl - c;
        g_deg[i] = (float)(c > 0 ? c : 1);
        if (i == 0) g_rowptr[0] = 0;
    }
}

// ---------------- K5: scatter edges into CSR, with precomputed scores --------
__global__ void k_scatter(){
    int e = blockIdx.x*blockDim.x + threadIdx.x;
    if (e >= EE) return;
    int s = g_eidx[e];
    int d = g_eidx[EE + e];
    int p = atomicAdd(&g_cursor[d], 1);
    g_esrc[p] = s;
    float4 a = g_ssrc4[s];
    float4 b = g_sdst4[d];
    float4 sc;
    sc.x = lrelu(a.x + b.x); sc.y = lrelu(a.y + b.y);
    sc.z = lrelu(a.z + b.z); sc.w = lrelu(a.w + b.w);
    g_escore[p] = sc;
}

// ---------------- K6: segment softmax + weighted aggregate + hop-1 -----------
__global__ void k_att(const float* __restrict__ x){
    int warp = threadIdx.x >> 5, lane = threadIdx.x & 31;
    int n = blockIdx.x*8 + warp;
    if (n >= NN) return;
    int beg = g_rowptr[n], end = g_rowptr[n+1];
    size_t arow = (size_t)n*KTOT;
    if (beg == end) {
        float2 z = make_float2(0.f, 0.f);
#pragma unroll
        for (int h = 0; h < 4; h++) *(float2*)(g_A + arow + h*FF + lane*2) = z;
        *(float2*)(g_g1 + (size_t)n*FF + lane*2) = z;
        return;
    }
    const float NEG = -1e30f;
    float4 mx = make_float4(NEG, NEG, NEG, NEG);
    for (int j = beg + lane; j < end; j += 32) {
        float4 s = g_escore[j];
        mx.x = fmaxf(mx.x, s.x); mx.y = fmaxf(mx.y, s.y);
        mx.z = fmaxf(mx.z, s.z); mx.w = fmaxf(mx.w, s.w);
    }
    mx.x = wredmax(mx.x); mx.y = wredmax(mx.y);
    mx.z = wredmax(mx.z); mx.w = wredmax(mx.w);
    float4 den = make_float4(0.f, 0.f, 0.f, 0.f);
    for (int j = beg + lane; j < end; j += 32) {
        float4 s = g_escore[j];
        float4 e;
        e.x = __expf(s.x - mx.x); e.y = __expf(s.y - mx.y);
        e.z = __expf(s.z - mx.z); e.w = __expf(s.w - mx.w);
        den.x += e.x; den.y += e.y; den.z += e.z; den.w += e.w;
        g_escore[j] = e;
    }
    den.x = wredsum(den.x); den.y = wredsum(den.y);
    den.z = wredsum(den.z); den.w = wredsum(den.w);
    __syncwarp();
    float4 inv;
    inv.x = 1.f/fmaxf(den.x, 1e-16f); inv.y = 1.f/fmaxf(den.y, 1e-16f);
    inv.z = 1.f/fmaxf(den.z, 1e-16f); inv.w = 1.f/fmaxf(den.w, 1e-16f);

    float2 a0 = make_float2(0,0), a1 = a0, a2 = a0, a3 = a0, ag = a0;
    for (int j = beg; j < end; j++) {
        int s = g_esrc[j];              // uniform across warp -> broadcast
        float4 al = g_escore[j];        // uniform across warp
        float2 v = *(const float2*)(x + (size_t)s*FF + lane*2);
        a0.x += al.x*v.x; a0.y += al.x*v.y;
        a1.x += al.y*v.x; a1.y += al.y*v.y;
        a2.x += al.z*v.x; a2.y += al.z*v.y;
        a3.x += al.w*v.x; a3.y += al.w*v.y;
        ag.x += v.x;      ag.y += v.y;
    }
    *(float2*)(g_A + arow + 0*FF + lane*2) = make_float2(a0.x*inv.x, a0.y*inv.x);
    *(float2*)(g_A + arow + 1*FF + lane*2) = make_float2(a1.x*inv.y, a1.y*inv.y);
    *(float2*)(g_A + arow + 2*FF + lane*2) = make_float2(a2.x*inv.z, a2.y*inv.z);
    *(float2*)(g_A + arow + 3*FF + lane*2) = make_float2(a3.x*inv.w, a3.y*inv.w);
    float dinv = 1.f / g_deg[n];
    *(float2*)(g_g1 + (size_t)n*FF + lane*2) = make_float2(ag.x*dinv, ag.y*dinv);
}

// ---------------- K7: hop-2 mean aggregation into A cols 256..319 ------------
__global__ void k_hop2(){
    int warp = threadIdx.x >> 5, lane = threadIdx.x & 31;
    int n = blockIdx.x*8 + warp;
    if (n >= NN) return;
    int beg = g_rowptr[n], end = g_rowptr[n+1];
    float2 ag = make_float2(0.f, 0.f);
    for (int j = beg; j < end; j++) {
        int s = g_esrc[j];
        float2 v = *(const float2*)(g_g1 + (size_t)s*FF + lane*2);
        ag.x += v.x; ag.y += v.y;
    }
    float dinv = 1.f / g_deg[n];
    *(float2*)(g_A + (size_t)n*KTOT + 256 + lane*2) = make_float2(ag.x*dinv, ag.y*dinv);
}

// ---------------- K8: out = A[N,320] @ Mall[320,64] + bias  (fp32 FMA) -------
// Block tile: 128 rows x 64 cols, 128 threads, 8x8 per-thread tile.
__global__ __launch_bounds__(128) void k_gemm(float* __restrict__ out){
    __shared__ float As[16][132];
    __shared__ float Bs[16][68];
    int t = threadIdx.x;
    int tx = t & 7;                 // col group: 8 groups x 8 cols
    int ty = t >> 3;                // row group: 16 groups x 8 rows
    int blockRow = blockIdx.x * 128;

    float acc[8][8];
#pragma unroll
    for (int i = 0; i < 8; i++)
#pragma unroll
        for (int j = 0; j < 8; j++) acc[i][j] = 0.f;

    int arow_l = t >> 2;            // 0..31
    int akc_l  = (t & 3) * 4;      // 0,4,8,12
    int brow_l = t >> 4;            // 0..7
    int bnc_l  = (t & 15) * 4;     // 0..60

    for (int kb = 0; kb < KTOT; kb += 16) {
#pragma unroll
        for (int p = 0; p < 4; p++) {
            int r = arow_l + p*32;
            int gr = blockRow + r;
            float4 v = make_float4(0.f, 0.f, 0.f, 0.f);
            if (gr < NN) v = *(const float4*)(g_A + (size_t)gr*KTOT + kb + akc_l);
            As[akc_l    ][r] = v.x;
            As[akc_l + 1][r] = v.y;
            As[akc_l + 2][r] = v.z;
            As[akc_l + 3][r] = v.w;
        }
#pragma unroll
        for (int p = 0; p < 2; p++) {
            int kr = brow_l + p*8;
            float4 v = *(const float4*)(g_Mall + (size_t)(kb + kr)*FF + bnc_l);
            *(float4*)&Bs[kr][bnc_l] = v;
        }
        __syncthreads();
#pragma unroll
        for (int k = 0; k < 16; k++) {
            float4 a0 = *(float4*)&As[k][ty*8];
            float4 a1 = *(float4*)&As[k][ty*8 + 4];
            float4 b0 = *(float4*)&Bs[k][tx*8];
            float4 b1 = *(float4*)&Bs[k][tx*8 + 4];
            float av[8] = {a0.x, a0.y, a0.z, a0.w, a1.x, a1.y, a1.z, a1.w};
            float bv[8] = {b0.x, b0.y, b0.z, b0.w, b1.x, b1.y, b1.z, b1.w};
#pragma unroll
            for (int i = 0; i < 8; i++)
#pragma unroll
                for (int j = 0; j < 8; j++) acc[i][j] += av[i] * bv[j];
        }
        __syncthreads();
    }
    float bsv[8];
#pragma unroll
    for (int j = 0; j < 8; j++) bsv[j] = g_bias[tx*8 + j];
#pragma unroll
    for (int i = 0; i < 8; i++) {
        int gr = blockRow + ty*8 + i;
        if (gr < NN) {
            float4 o0 = make_float4(acc[i][0]+bsv[0], acc[i][1]+bsv[1],
                                    acc[i][2]+bsv[2], acc[i][3]+bsv[3]);
            float4 o1 = make_float4(acc[i][4]+bsv[4], acc[i][5]+bsv[5],
                                    acc[i][6]+bsv[6], acc[i][7]+bsv[7]);
            *(float4*)(out + (size_t)gr*FF + tx*8)     = o0;
            *(float4*)(out + (size_t)gr*FF + tx*8 + 4) = o1;
        }
    }
}

// ---------------- launch ------------------------------------------------------
extern "C" void kernel_launch(void* const* d_in, const int* in_sizes, int n_in,
                              void* d_out, int out_size){
    const float* x     = (const float*)d_in[0];
    const void*  ei    = d_in[1];
    const float* W_att = (const float*)d_in[2];
    const float* a_src = (const float*)d_in[3];
    const float* a_dst = (const float*)d_in[4];
    const float* W_g   = (const float*)d_in[5];
    const float* b_g   = (const float*)d_in[6];
    const float* W_w   = (const float*)d_in[7];
    const float* b_w   = (const float*)d_in[8];
    float* out = (float*)d_out;

    k_zero   <<<(NN + 255)/256, 256>>>();
    k_decode <<<(2*EE + 255)/256, 256>>>(ei);   // detect + decode + hist
    k_wvec   <<<8, 64>>>(W_att, a_src, a_dst);
    k_mall   <<<84, 256>>>(W_att, W_g, W_w, b_g, b_w);
    k_score  <<<(NN + 7)/8, 256>>>(x);
    k_scan1  <<<SCAN_B, 1024>>>();
    k_scan2  <<<1, 128>>>();
    k_scan3  <<<SCAN_B, 1024>>>();
    k_scatter<<<(EE + 255)/256, 256>>>();
    k_att    <<<(NN + 7)/8, 256>>>(x);
    k_hop2   <<<(NN + 7)/8, 256>>>();
    k_gemm   <<<(NN + 127)/128, 128>>>(out);
}

// round 8
// speedup vs baseline: 1.1758x; 1.1072x over previous
#include <cuda_runtime.h>
#include <cstdint>

#define NN 100000
#define EE 800000
#define HH 4
#define FF 64
#define KTOT 320          // 4*64 (attention heads) + 64 (global branch)
#define SCAN_B 98         // ceil(100000/1024)

// ---------------- device scratch (static: no runtime allocation) -------------
__device__ __align__(16) float g_wsrc[HH*FF];
__device__ __align__(16) float g_wdst[HH*FF];
__device__ __align__(16) float g_Mall[KTOT*FF];   // combined projection [k][o]
__device__ __align__(16) unsigned g_Bfrag[40*8*32*2];  // tf32 B fragments, mma order
__device__ __align__(16) float g_bias[FF];
__device__ __align__(16) float4 g_ssrc4[NN];
__device__ __align__(16) float4 g_sdst4[NN];
__device__ int   g_eidx[2*EE];    // decoded edge indices: [src row | dst row]
__device__ int   g_cnt[NN];
__device__ int   g_rowptr[NN+1];
__device__ int   g_cursor[NN];
__device__ int   g_bsum[SCAN_B];
__device__ float g_deg[NN];
__device__ int   g_esrc[EE];
__device__ __align__(16) float4 g_escore[EE];
__device__ __align__(16) float g_A[(size_t)NN*KTOT];  // [N][320]: agg heads | g2
__device__ __align__(16) float g_g1[(size_t)NN*FF];

// ---------------- helpers ----------------------------------------------------
__device__ __forceinline__ float wredmax(float v){
#pragma unroll
    for (int o = 16; o > 0; o >>= 1) v = fmaxf(v, __shfl_xor_sync(0xffffffffu, v, o));
    return v;
}
__device__ __forceinline__ float wredsum(float v){
#pragma unroll
    for (int o = 16; o > 0; o >>= 1) v += __shfl_xor_sync(0xffffffffu, v, o);
    return v;
}
__device__ __forceinline__ unsigned f2tf32(float f){
    unsigned r; asm("cvt.rna.tf32.f32 %0, %1;" : "=r"(r) : "f"(f)); return r;
}
__device__ __forceinline__ float lrelu(float v){ return v > 0.f ? v : 0.2f * v; }

// ---------------- K1: decode (+dtype detect) + dst histogram -----------------
__global__ void k_decode(const void* __restrict__ ei){
    int lane = threadIdx.x & 31;
    int probe = ((const int*)ei)[2*lane + 1];
    bool is64 = (__ballot_sync(0xffffffffu, probe != 0) == 0u);
    int e = blockIdx.x*blockDim.x + threadIdx.x;
    if (e >= 2*EE) return;
    int v;
    if (is64) v = (int)((const long long*)ei)[e];
    else      v = ((const int*)ei)[e];
    v = (v < 0) ? 0 : (v >= NN ? NN-1 : v);   // defensive clamp
    g_eidx[e] = v;
    if (e >= EE) atomicAdd(&g_cnt[v], 1);     // dst histogram fused
}

// ---------------- K0: zero histogram (must precede k_decode) -----------------
__global__ void k_zero(){
    int i = blockIdx.x*blockDim.x + threadIdx.x;
    if (i < NN) g_cnt[i] = 0;
}

// ---------------- K2a: w_src/w_dst = W_att[h] @ a_{src,dst}[h] ---------------
__global__ void k_wvec(const float* __restrict__ W_att,
                       const float* __restrict__ a_src,
                       const float* __restrict__ a_dst){
    int b = blockIdx.x;           // 0..7
    int h = b >> 1, sel = b & 1;
    int i = threadIdx.x;          // 0..63
    const float* W = W_att + (size_t)h*FF*FF + (size_t)i*FF;
    const float* a = (sel ? a_dst : a_src) + h*FF;
    float s = 0.f;
#pragma unroll
    for (int o = 0; o < FF; o++) s += W[o]*a[o];
    (sel ? g_wdst : g_wsrc)[h*FF + i] = s;
}

// ---------------- K2b: Mall rows + bias (4 rows per 256-thread block) --------
__global__ __launch_bounds__(256) void k_mall(const float* __restrict__ W_att,
                       const float* __restrict__ W_g,
                       const float* __restrict__ W_w,
                       const float* __restrict__ b_g,
                       const float* __restrict__ b_w){
    int r = blockIdx.x*4 + (threadIdx.x >> 6);  // 0..335 (valid 0..320)
    int o = threadIdx.x & 63;
    if (r > 320) return;
    if (r < 256) {
        int h = r >> 6, i = r & 63;
        const float* wa = W_att + (size_t)h*FF*FF + (size_t)i*FF;
        float s = 0.f;
#pragma unroll
        for (int j = 0; j < FF; j++) s += wa[j] * W_w[(size_t)j*FF + o];
        g_Mall[(size_t)r*FF + o] = 0.25f * s;
    } else if (r < 320) {
        int i = r - 256;
        float s = 0.f;
#pragma unroll
        for (int j = 0; j < FF; j++) s += W_g[(size_t)i*FF + j] * W_w[(size_t)(FF+j)*FF + o];
        g_Mall[(size_t)r*FF + o] = s;
    } else {
        float s = b_w[o];
#pragma unroll
        for (int j = 0; j < FF; j++) s += b_g[j] * W_w[(size_t)(FF+j)*FF + o];
        g_bias[o] = s;
    }
}

// ---------------- K2c: permute Mall into tf32 mma B-fragments ----------------
// m16n8k8.row.col B frag: lane = gid*4+tig holds {B[k=tig][n=gid], B[k=tig+4][n=gid]}
__global__ void k_bfrag(){
    int c = blockIdx.x;           // k8 chunk 0..39
    int t = threadIdx.x;          // 0..255
    int n8 = t >> 5, lane = t & 31;
    int tig = lane & 3, gid = lane >> 2;
    int n = n8*8 + gid;
    float b0 = g_Mall[(size_t)(c*8 + tig    )*FF + n];
    float b1 = g_Mall[(size_t)(c*8 + tig + 4)*FF + n];
    size_t idx = ((size_t)(c*8 + n8)*32 + lane)*2;
    g_Bfrag[idx]   = f2tf32(b0);
    g_Bfrag[idx+1] = f2tf32(b1);
}

// ---------------- K3: per-node attention logits s_src/s_dst ------------------
__global__ void k_score(const float* __restrict__ x){
    int warp = threadIdx.x >> 5, lane = threadIdx.x & 31;
    int n = blockIdx.x*8 + warp;
    if (n >= NN) return;
    float2 xv = *(const float2*)(x + (size_t)n*FF + lane*2);
    float p[8];
#pragma unroll
    for (int h = 0; h < 4; h++) {
        float2 w = *(const float2*)(g_wsrc + h*FF + lane*2);
        p[h] = xv.x*w.x + xv.y*w.y;
    }
#pragma unroll
    for (int h = 0; h < 4; h++) {
        float2 w = *(const float2*)(g_wdst + h*FF + lane*2);
        p[4+h] = xv.x*w.x + xv.y*w.y;
    }
#pragma unroll
    for (int k = 0; k < 8; k++) p[k] = wredsum(p[k]);
    if (lane == 0) {
        g_ssrc4[n] = make_float4(p[0], p[1], p[2], p[3]);
        g_sdst4[n] = make_float4(p[4], p[5], p[6], p[7]);
    }
}

// ---------------- K4: scan (3 stages, shfl-based) ----------------------------
__global__ void k_scan1(){
    __shared__ int wsum[32];
    int t = threadIdx.x, lane = t & 31, w = t >> 5;
    int i = blockIdx.x*1024 + t;
    int v = (i < NN) ? g_cnt[i] : 0;
    int xv = v;
#pragma unroll
    for (int o = 1; o < 32; o <<= 1) {
        int u = __shfl_up_sync(0xffffffffu, xv, o);
        if (lane >= o) xv += u;
    }
    if (lane == 31) wsum[w] = xv;
    __syncthreads();
    if (w == 0) {
        int y = wsum[lane];
#pragma unroll
        for (int o = 1; o < 32; o <<= 1) {
            int u = __shfl_up_sync(0xffffffffu, y, o);
            if (lane >= o) y += u;
        }
        wsum[lane] = y;
    }
    __syncthreads();
    int incl = xv + (w > 0 ? wsum[w-1] : 0);
    if (i < NN) g_rowptr[i+1] = incl;
    if (t == 1023) g_bsum[blockIdx.x] = incl;
}
__global__ void k_scan2(){          // 1 block, 128 threads, exclusive scan
    __shared__ int wsum[4];
    int t = threadIdx.x, lane = t & 31, w = t >> 5;
    int v = (t < SCAN_B) ? g_bsum[t] : 0;
    int xv = v;
#pragma unroll
    for (int o = 1; o < 32; o <<= 1) {
        int u = __shfl_up_sync(0xffffffffu, xv, o);
        if (lane >= o) xv += u;
    }
    if (lane == 31) wsum[w] = xv;
    __syncthreads();
    int pre = 0;
#pragma unroll
    for (int k = 0; k < 4; k++) if (k < w) pre += wsum[k];
    if (t < SCAN_B) g_bsum[t] = xv + pre - v;   // exclusive
}
__global__ void k_scan3(){
    int t = threadIdx.x;
    int i = blockIdx.x*1024 + t;
    if (i < NN) {
        int incl = g_rowptr[i+1] + g_bsum[blockIdx.x];
        g_rowptr[i+1] = incl;
        int c = g_cnt[i];
        g_cursor[i] = incl - c;
        g_deg[i] = (float)(c > 0 ? c : 1);
        if (i == 0) g_rowptr[0] = 0;
    }
}

// ---------------- K5: scatter edges into CSR, with precomputed scores --------
__global__ void k_scatter(){
    int e = blockIdx.x*blockDim.x + threadIdx.x;
    if (e >= EE) return;
    int s = g_eidx[e];
    int d = g_eidx[EE + e];
    int p = atomicAdd(&g_cursor[d], 1);
    g_esrc[p] = s;
    float4 a = g_ssrc4[s];
    float4 b = g_sdst4[d];
    float4 sc;
    sc.x = lrelu(a.x + b.x); sc.y = lrelu(a.y + b.y);
    sc.z = lrelu(a.z + b.z); sc.w = lrelu(a.w + b.w);
    g_escore[p] = sc;
}

// ---------------- K6: segment softmax + weighted aggregate + hop-1 -----------
__global__ void k_att(const float* __restrict__ x){
    int warp = threadIdx.x >> 5, lane = threadIdx.x & 31;
    int n = blockIdx.x*8 + warp;
    if (n >= NN) return;
    int beg = g_rowptr[n], end = g_rowptr[n+1];
    size_t arow = (size_t)n*KTOT;
    if (beg == end) {
        float2 z = make_float2(0.f, 0.f);
#pragma unroll
        for (int h = 0; h < 4; h++) *(float2*)(g_A + arow + h*FF + lane*2) = z;
        *(float2*)(g_g1 + (size_t)n*FF + lane*2) = z;
        return;
    }
    const float NEG = -1e30f;
    float4 mx = make_float4(NEG, NEG, NEG, NEG);
    for (int j = beg + lane; j < end; j += 32) {
        float4 s = g_escore[j];
        mx.x = fmaxf(mx.x, s.x); mx.y = fmaxf(mx.y, s.y);
        mx.z = fmaxf(mx.z, s.z); mx.w = fmaxf(mx.w, s.w);
    }
    mx.x = wredmax(mx.x); mx.y = wredmax(mx.y);
    mx.z = wredmax(mx.z); mx.w = wredmax(mx.w);
    float4 den = make_float4(0.f, 0.f, 0.f, 0.f);
    for (int j = beg + lane; j < end; j += 32) {
        float4 s = g_escore[j];
        float4 e;
        e.x = __expf(s.x - mx.x); e.y = __expf(s.y - mx.y);
        e.z = __expf(s.z - mx.z); e.w = __expf(s.w - mx.w);
        den.x += e.x; den.y += e.y; den.z += e.z; den.w += e.w;
        g_escore[j] = e;
    }
    den.x = wredsum(den.x); den.y = wredsum(den.y);
    den.z = wredsum(den.z); den.w = wredsum(den.w);
    __syncwarp();
    float4 inv;
    inv.x = 1.f/fmaxf(den.x, 1e-16f); inv.y = 1.f/fmaxf(den.y, 1e-16f);
    inv.z = 1.f/fmaxf(den.z, 1e-16f); inv.w = 1.f/fmaxf(den.w, 1e-16f);

    float2 a0 = make_float2(0,0), a1 = a0, a2 = a0, a3 = a0, ag = a0;
    for (int j = beg; j < end; j++) {
        int s = g_esrc[j];              // uniform across warp -> broadcast
        float4 al = g_escore[j];        // uniform across warp
        float2 v = *(const float2*)(x + (size_t)s*FF + lane*2);
        a0.x += al.x*v.x; a0.y += al.x*v.y;
        a1.x += al.y*v.x; a1.y += al.y*v.y;
        a2.x += al.z*v.x; a2.y += al.z*v.y;
        a3.x += al.w*v.x; a3.y += al.w*v.y;
        ag.x += v.x;      ag.y += v.y;
    }
    *(float2*)(g_A + arow + 0*FF + lane*2) = make_float2(a0.x*inv.x, a0.y*inv.x);
    *(float2*)(g_A + arow + 1*FF + lane*2) = make_float2(a1.x*inv.y, a1.y*inv.y);
    *(float2*)(g_A + arow + 2*FF + lane*2) = make_float2(a2.x*inv.z, a2.y*inv.z);
    *(float2*)(g_A + arow + 3*FF + lane*2) = make_float2(a3.x*inv.w, a3.y*inv.w);
    float dinv = 1.f / g_deg[n];
    *(float2*)(g_g1 + (size_t)n*FF + lane*2) = make_float2(ag.x*dinv, ag.y*dinv);
}

// ---------------- K7: hop-2 mean aggregation into A cols 256..319 ------------
__global__ void k_hop2(){
    int warp = threadIdx.x >> 5, lane = threadIdx.x & 31;
    int n = blockIdx.x*8 + warp;
    if (n >= NN) return;
    int beg = g_rowptr[n], end = g_rowptr[n+1];
    float2 ag = make_float2(0.f, 0.f);
    for (int j = beg; j < end; j++) {
        int s = g_esrc[j];
        float2 v = *(const float2*)(g_g1 + (size_t)s*FF + lane*2);
        ag.x += v.x; ag.y += v.y;
    }
    float dinv = 1.f / g_deg[n];
    *(float2*)(g_A + (size_t)n*KTOT + 256 + lane*2) = make_float2(ag.x*dinv, ag.y*dinv);
}

// ---------------- K8: out = A[N,320] @ Mall[320,64] + bias  (tf32 mma) -------
// 256 threads = 8 warps, each warp: 32 rows x 64 cols. NO shared memory:
// A fragments loaded directly from global (8x32B sectors per LDG, L1 reuse for
// the tig+4 half); B fragments pre-packed in g_Bfrag (L1-resident, 80 KB).
__global__ __launch_bounds__(256) void k_gemm(float* __restrict__ out){
    int t = threadIdx.x, warp = t >> 5, lane = t & 31;
    int gid = lane >> 2, tig = lane & 3;
    int rowBase = blockIdx.x*256 + warp*32;

    float c[2][8][4];
#pragma unroll
    for (int mt = 0; mt < 2; mt++)
#pragma unroll
        for (int nt = 0; nt < 8; nt++)
#pragma unroll
            for (int i = 0; i < 4; i++) c[mt][nt][i] = 0.f;

#pragma unroll 2
    for (int cch = 0; cch < 40; cch++) {
        // B fragments for this k-chunk: 8 n-tiles x 2 regs (LDG.64, L1-hot)
        unsigned b[8][2];
        const unsigned* bp = g_Bfrag + (size_t)cch*512 + lane*2;
#pragma unroll
        for (int nt = 0; nt < 8; nt++) { b[nt][0] = bp[nt*64]; b[nt][1] = bp[nt*64 + 1]; }

#pragma unroll
        for (int mt = 0; mt < 2; mt++) {
            int r0 = rowBase + mt*16 + gid;
            int r1 = r0 + 8;
            int k0 = cch*8 + tig;
            unsigned ua0 = 0u, ua1 = 0u, ua2 = 0u, ua3 = 0u;
            if (r0 < NN) {
                ua0 = f2tf32(g_A[(size_t)r0*KTOT + k0]);
                ua2 = f2tf32(g_A[(size_t)r0*KTOT + k0 + 4]);
            }
            if (r1 < NN) {
                ua1 = f2tf32(g_A[(size_t)r1*KTOT + k0]);
                ua3 = f2tf32(g_A[(size_t)r1*KTOT + k0 + 4]);
            }
#pragma unroll
            for (int nt = 0; nt < 8; nt++) {
                asm volatile(
                    "mma.sync.aligned.m16n8k8.row.col.f32.tf32.tf32.f32 "
                    "{%0,%1,%2,%3},{%4,%5,%6,%7},{%8,%9},{%0,%1,%2,%3};"
                    : "+f"(c[mt][nt][0]), "+f"(c[mt][nt][1]),
                      "+f"(c[mt][nt][2]), "+f"(c[mt][nt][3])
                    : "r"(ua0), "r"(ua1), "r"(ua2), "r"(ua3),
                      "r"(b[nt][0]), "r"(b[nt][1]));
            }
        }
    }
    // epilogue: bias + float2 stores
#pragma unroll
    for (int mt = 0; mt < 2; mt++) {
#pragma unroll
        for (int nt = 0; nt < 8; nt++) {
            int col = nt*8 + tig*2;
            float b0 = g_bias[col], b1 = g_bias[col+1];
            int r0 = rowBase + mt*16 + gid;
            if (r0 < NN)
                *(float2*)(out + (size_t)r0*FF + col) =
                    make_float2(c[mt][nt][0] + b0, c[mt][nt][1] + b1);
            int r1 = r0 + 8;
            if (r1 < NN)
                *(float2*)(out + (size_t)r1*FF + col) =
                    make_float2(c[mt][nt][2] + b0, c[mt][nt][3] + b1);
        }
    }
}

// ---------------- launch ------------------------------------------------------
extern "C" void kernel_launch(void* const* d_in, const int* in_sizes, int n_in,
                              void* d_out, int out_size){
    const float* x     = (const float*)d_in[0];
    const void*  ei    = d_in[1];
    const float* W_att = (const float*)d_in[2];
    const float* a_src = (const float*)d_in[3];
    const float* a_dst = (const float*)d_in[4];
    const float* W_g   = (const float*)d_in[5];
    const float* b_g   = (const float*)d_in[6];
    const float* W_w   = (const float*)d_in[7];
    const float* b_w   = (const float*)d_in[8];
    float* out = (float*)d_out;

    k_zero   <<<(NN + 255)/256, 256>>>();
    k_decode <<<(2*EE + 255)/256, 256>>>(ei);   // detect + decode + hist
    k_wvec   <<<8, 64>>>(W_att, a_src, a_dst);
    k_mall   <<<84, 256>>>(W_att, W_g, W_w, b_g, b_w);
    k_bfrag  <<<40, 256>>>();
    k_score  <<<(NN + 7)/8, 256>>>(x);
    k_scan1  <<<SCAN_B, 1024>>>();
    k_scan2  <<<1, 128>>>();
    k_scan3  <<<SCAN_B, 1024>>>();
    k_scatter<<<(EE + 255)/256, 256>>>();
    k_att    <<<(NN + 7)/8, 256>>>(x);
    k_hop2   <<<(NN + 7)/8, 256>>>();
    k_gemm   <<<(NN + 255)/256, 256>>>(out);
}

// round 10
// speedup vs baseline: 1.4778x; 1.2568x over previous
#include <cuda_runtime.h>
#include <cuda_fp16.h>
#include <cstdint>

#define NN 100000
#define EE 800000
#define HH 4
#define FF 64
#define KTOT 320          // 4*64 (attention heads) + 64 (global branch)
#define SCAN_B 98         // ceil(100000/1024)

// ---------------- device scratch (static: no runtime allocation) -------------
__device__ __align__(16) float g_wsrc[HH*FF];
__device__ __align__(16) float g_wdst[HH*FF];
__device__ __align__(16) float g_Mall[KTOT*FF];   // combined projection [k][o]
__device__ __align__(16) unsigned g_BfragH[20*8*32*2];  // f16 B fragments, mma order
__device__ __align__(16) float g_bias[FF];
__device__ __align__(16) float4 g_ssrc4[NN];
__device__ __align__(16) float4 g_sdst4[NN];
__device__ int   g_eidx[2*EE];    // decoded edge indices: [src row | dst row]
__device__ int   g_cnt[NN];
__device__ int   g_rowptr[NN+1];
__device__ int   g_cursor[NN];
__device__ int   g_bsum[SCAN_B];
__device__ float g_deg[NN];
__device__ int   g_esrc[EE];
__device__ __align__(16) float4 g_escore[EE];
__device__ __align__(16) __half g_Ah[(size_t)NN*KTOT]; // [N][320] fp16: heads | g2
__device__ __align__(16) float g_g1[(size_t)NN*FF];

// ---------------- helpers ----------------------------------------------------
__device__ __forceinline__ float wredmax(float v){
#pragma unroll
    for (int o = 16; o > 0; o >>= 1) v = fmaxf(v, __shfl_xor_sync(0xffffffffu, v, o));
    return v;
}
__device__ __forceinline__ float wredsum(float v){
#pragma unroll
    for (int o = 16; o > 0; o >>= 1) v += __shfl_xor_sync(0xffffffffu, v, o);
    return v;
}
__device__ __forceinline__ float lrelu(float v){ return v > 0.f ? v : 0.2f * v; }
__device__ __forceinline__ void sth2(__half* p, float a, float b){
    *(half2*)p = __floats2half2_rn(a, b);
}

// ---------------- K1: decode (+dtype detect) + dst histogram -----------------
__global__ void k_decode(const void* __restrict__ ei){
    int lane = threadIdx.x & 31;
    int probe = ((const int*)ei)[2*lane + 1];
    bool is64 = (__ballot_sync(0xffffffffu, probe != 0) == 0u);
    int e = blockIdx.x*blockDim.x + threadIdx.x;
    if (e >= 2*EE) return;
    int v;
    if (is64) v = (int)((const long long*)ei)[e];
    else      v = ((const int*)ei)[e];
    v = (v < 0) ? 0 : (v >= NN ? NN-1 : v);   // defensive clamp
    g_eidx[e] = v;
    if (e >= EE) atomicAdd(&g_cnt[v], 1);     // dst histogram fused
}

// ---------------- K0: zero histogram (must precede k_decode) -----------------
__global__ void k_zero(){
    int i = blockIdx.x*blockDim.x + threadIdx.x;
    if (i < NN) g_cnt[i] = 0;
}

// ---------------- K2a: w_src/w_dst = W_att[h] @ a_{src,dst}[h] ---------------
__global__ void k_wvec(const float* __restrict__ W_att,
                       const float* __restrict__ a_src,
                       const float* __restrict__ a_dst){
    int b = blockIdx.x;           // 0..7
    int h = b >> 1, sel = b & 1;
    int i = threadIdx.x;          // 0..63
    const float* W = W_att + (size_t)h*FF*FF + (size_t)i*FF;
    const float* a = (sel ? a_dst : a_src) + h*FF;
    float s = 0.f;
#pragma unroll
    for (int o = 0; o < FF; o++) s += W[o]*a[o];
    (sel ? g_wdst : g_wsrc)[h*FF + i] = s;
}

// ---------------- K2b: Mall rows + bias (4 rows per 256-thread block) --------
__global__ __launch_bounds__(256) void k_mall(const float* __restrict__ W_att,
                       const float* __restrict__ W_g,
                       const float* __restrict__ W_w,
                       const float* __restrict__ b_g,
                       const float* __restrict__ b_w){
    int r = blockIdx.x*4 + (threadIdx.x >> 6);  // 0..335 (valid 0..320)
    int o = threadIdx.x & 63;
    if (r > 320) return;
    if (r < 256) {
        int h = r >> 6, i = r & 63;
        const float* wa = W_att + (size_t)h*FF*FF + (size_t)i*FF;
        float s = 0.f;
#pragma unroll
        for (int j = 0; j < FF; j++) s += wa[j] * W_w[(size_t)j*FF + o];
        g_Mall[(size_t)r*FF + o] = 0.25f * s;
    } else if (r < 320) {
        int i = r - 256;
        float s = 0.f;
#pragma unroll
        for (int j = 0; j < FF; j++) s += W_g[(size_t)i*FF + j] * W_w[(size_t)(FF+j)*FF + o];
        g_Mall[(size_t)r*FF + o] = s;
    } else {
        float s = b_w[o];
#pragma unroll
        for (int j = 0; j < FF; j++) s += b_g[j] * W_w[(size_t)(FF+j)*FF + o];
        g_bias[o] = s;
    }
}

// ---------------- K2c: pack Mall into f16 mma B-fragments (m16n8k16) ---------
// row.col B frag (16x8): b0 = {B[2tig][gid], B[2tig+1][gid]},
//                        b1 = {B[2tig+8][gid], B[2tig+9][gid]}
__global__ void k_bfragH(){
    int c = blockIdx.x;           // k16 chunk 0..19
    int t = threadIdx.x;          // 0..255
    int n8 = t >> 5, lane = t & 31;
    int tig = lane & 3, gid = lane >> 2;
    int n = n8*8 + gid;
    int k0 = c*16 + 2*tig;
    half2 b0 = __floats2half2_rn(g_Mall[(size_t)(k0    )*FF + n],
                                 g_Mall[(size_t)(k0 + 1)*FF + n]);
    half2 b1 = __floats2half2_rn(g_Mall[(size_t)(k0 + 8)*FF + n],
                                 g_Mall[(size_t)(k0 + 9)*FF + n]);
    size_t idx = ((size_t)(c*8 + n8)*32 + lane)*2;
    g_BfragH[idx]   = *(unsigned*)&b0;
    g_BfragH[idx+1] = *(unsigned*)&b1;
}

// ---------------- K3: per-node attention logits s_src/s_dst ------------------
__global__ void k_score(const float* __restrict__ x){
    int warp = threadIdx.x >> 5, lane = threadIdx.x & 31;
    int n = blockIdx.x*8 + warp;
    if (n >= NN) return;
    float2 xv = *(const float2*)(x + (size_t)n*FF + lane*2);
    float p[8];
#pragma unroll
    for (int h = 0; h < 4; h++) {
        float2 w = *(const float2*)(g_wsrc + h*FF + lane*2);
        p[h] = xv.x*w.x + xv.y*w.y;
    }
#pragma unroll
    for (int h = 0; h < 4; h++) {
        float2 w = *(const float2*)(g_wdst + h*FF + lane*2);
        p[4+h] = xv.x*w.x + xv.y*w.y;
    }
#pragma unroll
    for (int k = 0; k < 8; k++) p[k] = wredsum(p[k]);
    if (lane == 0) {
        g_ssrc4[n] = make_float4(p[0], p[1], p[2], p[3]);
        g_sdst4[n] = make_float4(p[4], p[5], p[6], p[7]);
    }
}

// ---------------- K4: scan (3 stages, shfl-based) ----------------------------
__global__ void k_scan1(){
    __shared__ int wsum[32];
    int t = threadIdx.x, lane = t & 31, w = t >> 5;
    int i = blockIdx.x*1024 + t;
    int v = (i < NN) ? g_cnt[i] : 0;
    int xv = v;
#pragma unroll
    for (int o = 1; o < 32; o <<= 1) {
        int u = __shfl_up_sync(0xffffffffu, xv, o);
        if (lane >= o) xv += u;
    }
    if (lane == 31) wsum[w] = xv;
    __syncthreads();
    if (w == 0) {
        int y = wsum[lane];
#pragma unroll
        for (int o = 1; o < 32; o <<= 1) {
            int u = __shfl_up_sync(0xffffffffu, y, o);
            if (lane >= o) y += u;
        }
        wsum[lane] = y;
    }
    __syncthreads();
    int incl = xv + (w > 0 ? wsum[w-1] : 0);
    if (i < NN) g_rowptr[i+1] = incl;
    if (t == 1023) g_bsum[blockIdx.x] = incl;
}
__global__ void k_scan2(){          // 1 block, 128 threads, exclusive scan
    __shared__ int wsum[4];
    int t = threadIdx.x, lane = t & 31, w = t >> 5;
    int v = (t < SCAN_B) ? g_bsum[t] : 0;
    int xv = v;
#pragma unroll
    for (int o = 1; o < 32; o <<= 1) {
        int u = __shfl_up_sync(0xffffffffu, xv, o);
        if (lane >= o) xv += u;
    }
    if (lane == 31) wsum[w] = xv;
    __syncthreads();
    int pre = 0;
#pragma unroll
    for (int k = 0; k < 4; k++) if (k < w) pre += wsum[k];
    if (t < SCAN_B) g_bsum[t] = xv + pre - v;   // exclusive
}
__global__ void k_scan3(){
    int t = threadIdx.x;
    int i = blockIdx.x*1024 + t;
    if (i < NN) {
        int incl = g_rowptr[i+1] + g_bsum[blockIdx.x];
        g_rowptr[i+1] = incl;
        int c = g_cnt[i];
        g_cursor[i] = incl - c;
        g_deg[i] = (float)(c > 0 ? c : 1);
        if (i == 0) g_rowptr[0] = 0;
    }
}

// ---------------- K5: scatter edges into CSR, with precomputed scores --------
__global__ void k_scatter(){
    int e = blockIdx.x*blockDim.x + threadIdx.x;
    if (e >= EE) return;
    int s = g_eidx[e];
    int d = g_eidx[EE + e];
    int p = atomicAdd(&g_cursor[d], 1);
    g_esrc[p] = s;
    float4 a = g_ssrc4[s];
    float4 b = g_sdst4[d];
    float4 sc;
    sc.x = lrelu(a.x + b.x); sc.y = lrelu(a.y + b.y);
    sc.z = lrelu(a.z + b.z); sc.w = lrelu(a.w + b.w);
    g_escore[p] = sc;
}

// ---------------- K6: segment softmax + weighted aggregate + hop-1 -----------
__global__ void k_att(const float* __restrict__ x){
    int warp = threadIdx.x >> 5, lane = threadIdx.x & 31;
    int n = blockIdx.x*8 + warp;
    if (n >= NN) return;
    int beg = g_rowptr[n], end = g_rowptr[n+1];
    size_t arow = (size_t)n*KTOT;
    if (beg == end) {
#pragma unroll
        for (int h = 0; h < 4; h++) sth2(g_Ah + arow + h*FF + lane*2, 0.f, 0.f);
        *(float2*)(g_g1 + (size_t)n*FF + lane*2) = make_float2(0.f, 0.f);
        return;
    }
    const float NEG = -1e30f;
    float4 mx = make_float4(NEG, NEG, NEG, NEG);
    for (int j = beg + lane; j < end; j += 32) {
        float4 s = g_escore[j];
        mx.x = fmaxf(mx.x, s.x); mx.y = fmaxf(mx.y, s.y);
        mx.z = fmaxf(mx.z, s.z); mx.w = fmaxf(mx.w, s.w);
    }
    mx.x = wredmax(mx.x); mx.y = wredmax(mx.y);
    mx.z = wredmax(mx.z); mx.w = wredmax(mx.w);
    float4 den = make_float4(0.f, 0.f, 0.f, 0.f);
    for (int j = beg + lane; j < end; j += 32) {
        float4 s = g_escore[j];
        float4 e;
        e.x = __expf(s.x - mx.x); e.y = __expf(s.y - mx.y);
        e.z = __expf(s.z - mx.z); e.w = __expf(s.w - mx.w);
        den.x += e.x; den.y += e.y; den.z += e.z; den.w += e.w;
        g_escore[j] = e;
    }
    den.x = wredsum(den.x); den.y = wredsum(den.y);
    den.z = wredsum(den.z); den.w = wredsum(den.w);
    __syncwarp();
    float4 inv;
    inv.x = 1.f/fmaxf(den.x, 1e-16f); inv.y = 1.f/fmaxf(den.y, 1e-16f);
    inv.z = 1.f/fmaxf(den.z, 1e-16f); inv.w = 1.f/fmaxf(den.w, 1e-16f);

    float2 a0 = make_float2(0,0), a1 = a0, a2 = a0, a3 = a0, ag = a0;
    for (int j = beg; j < end; j++) {
        int s = g_esrc[j];              // uniform across warp -> broadcast
        float4 al = g_escore[j];        // uniform across warp
        float2 v = *(const float2*)(x + (size_t)s*FF + lane*2);
        a0.x += al.x*v.x; a0.y += al.x*v.y;
        a1.x += al.y*v.x; a1.y += al.y*v.y;
        a2.x += al.z*v.x; a2.y += al.z*v.y;
        a3.x += al.w*v.x; a3.y += al.w*v.y;
        ag.x += v.x;      ag.y += v.y;
    }
    sth2(g_Ah + arow + 0*FF + lane*2, a0.x*inv.x, a0.y*inv.x);
    sth2(g_Ah + arow + 1*FF + lane*2, a1.x*inv.y, a1.y*inv.y);
    sth2(g_Ah + arow + 2*FF + lane*2, a2.x*inv.z, a2.y*inv.z);
    sth2(g_Ah + arow + 3*FF + lane*2, a3.x*inv.w, a3.y*inv.w);
    float dinv = 1.f / g_deg[n];
    *(float2*)(g_g1 + (size_t)n*FF + lane*2) = make_float2(ag.x*dinv, ag.y*dinv);
}

// ---------------- K7: hop-2 mean aggregation into A cols 256..319 ------------
__global__ void k_hop2(){
    int warp = threadIdx.x >> 5, lane = threadIdx.x & 31;
    int n = blockIdx.x*8 + warp;
    if (n >= NN) return;
    int beg = g_rowptr[n], end = g_rowptr[n+1];
    float2 ag = make_float2(0.f, 0.f);
    for (int j = beg; j < end; j++) {
        int s = g_esrc[j];
        float2 v = *(const float2*)(g_g1 + (size_t)s*FF + lane*2);
        ag.x += v.x; ag.y += v.y;
    }
    float dinv = 1.f / g_deg[n];
    sth2(g_Ah + (size_t)n*KTOT + 256 + lane*2, ag.x*dinv, ag.y*dinv);
}

// ---------------- K8: out = A[N,320] @ Mall[320,64] + bias  (f16 mma k16) ----
// 256 threads = 8 warps, each warp: 32 rows x 64 cols. No shared memory:
// A fragments via direct LDG.32 of half2 pairs; B pre-packed in g_BfragH.
__global__ __launch_bounds__(256) void k_gemm(float* __restrict__ out){
    int t = threadIdx.x, warp = t >> 5, lane = t & 31;
    int gid = lane >> 2, tig = lane & 3;
    int rowBase = blockIdx.x*256 + warp*32;

    float c[2][8][4];
#pragma unroll
    for (int mt = 0; mt < 2; mt++)
#pragma unroll
        for (int nt = 0; nt < 8; nt++)
#pragma unroll
            for (int i = 0; i < 4; i++) c[mt][nt][i] = 0.f;

#pragma unroll 2
    for (int cch = 0; cch < 20; cch++) {
        // B fragments for this k16-chunk: 8 n-tiles x 2 regs (L1-hot)
        unsigned b[8][2];
        const unsigned* bp = g_BfragH + (size_t)cch*512 + lane*2;
#pragma unroll
        for (int nt = 0; nt < 8; nt++) { b[nt][0] = bp[nt*64]; b[nt][1] = bp[nt*64 + 1]; }

#pragma unroll
        for (int mt = 0; mt < 2; mt++) {
            int r0 = rowBase + mt*16 + gid;
            int r1 = r0 + 8;
            int k0 = cch*16 + 2*tig;
            unsigned ua0 = 0u, ua1 = 0u, ua2 = 0u, ua3 = 0u;
            if (r0 < NN) {
                ua0 = *(const unsigned*)(g_Ah + (size_t)r0*KTOT + k0);
                ua2 = *(const unsigned*)(g_Ah + (size_t)r0*KTOT + k0 + 8);
            }
            if (r1 < NN) {
                ua1 = *(const unsigned*)(g_Ah + (size_t)r1*KTOT + k0);
                ua3 = *(const unsigned*)(g_Ah + (size_t)r1*KTOT + k0 + 8);
            }
#pragma unroll
            for (int nt = 0; nt < 8; nt++) {
                asm volatile(
                    "mma.sync.aligned.m16n8k16.row.col.f32.f16.f16.f32 "
                    "{%0,%1,%2,%3},{%4,%5,%6,%7},{%8,%9},{%0,%1,%2,%3};"
                    : "+f"(c[mt][nt][0]), "+f"(c[mt][nt][1]),
                      "+f"(c[mt][nt][2]), "+f"(c[mt][nt][3])
                    : "r"(ua0), "r"(ua1), "r"(ua2), "r"(ua3),
                      "r"(b[nt][0]), "r"(b[nt][1]));
            }
        }
    }
    // epilogue: bias + float2 stores
#pragma unroll
    for (int mt = 0; mt < 2; mt++) {
#pragma unroll
        for (int nt = 0; nt < 8; nt++) {
            int col = nt*8 + tig*2;
            float b0 = g_bias[col], b1 = g_bias[col+1];
            int r0 = rowBase + mt*16 + gid;
            if (r0 < NN)
                *(float2*)(out + (size_t)r0*FF + col) =
                    make_float2(c[mt][nt][0] + b0, c[mt][nt][1] + b1);
            int r1 = r0 + 8;
            if (r1 < NN)
                *(float2*)(out + (size_t)r1*FF + col) =
                    make_float2(c[mt][nt][2] + b0, c[mt][nt][3] + b1);
        }
    }
}

// ---------------- launch ------------------------------------------------------
extern "C" void kernel_launch(void* const* d_in, const int* in_sizes, int n_in,
                              void* d_out, int out_size){
    const float* x     = (const float*)d_in[0];
    const void*  ei    = d_in[1];
    const float* W_att = (const float*)d_in[2];
    const float* a_src = (const float*)d_in[3];
    const float* a_dst = (const float*)d_in[4];
    const float* W_g   = (const float*)d_in[5];
    const float* b_g   = (const float*)d_in[6];
    const float* W_w   = (const float*)d_in[7];
    const float* b_w   = (const float*)d_in[8];
    float* out = (float*)d_out;

    k_zero   <<<(NN + 255)/256, 256>>>();
    k_decode <<<(2*EE + 255)/256, 256>>>(ei);   // detect + decode + hist
    k_wvec   <<<8, 64>>>(W_att, a_src, a_dst);
    k_mall   <<<84, 256>>>(W_att, W_g, W_w, b_g, b_w);
    k_bfragH <<<20, 256>>>();
    k_score  <<<(NN + 7)/8, 256>>>(x);
    k_scan1  <<<SCAN_B, 1024>>>();
    k_scan2  <<<1, 128>>>();
    k_scan3  <<<SCAN_B, 1024>>>();
    k_scatter<<<(EE + 255)/256, 256>>>();
    k_att    <<<(NN + 7)/8, 256>>>(x);
    k_hop2   <<<(NN + 7)/8, 256>>>();
    k_gemm   <<<(NN + 255)/256, 256>>>(out);
}